// round 8
// baseline (speedup 1.0000x reference)
#include <cuda_runtime.h>
#include <cuda_fp16.h>

// SatelliteImageGNN: 3-layer GCN on a 768x768 8-neighbor grid + 3x pixel shuffle.
//
// Transform: with dinv = 1/sqrt(deg) (position-determined on the grid),
//   layer(h) = (dinv .* BoxSum3x3(dinv .* h)) @ W + b
// edge_index is never read.
//
// R8 = R7 (fused, fp16-staged, constant weights) +
//   - GEMMs in packed fma.rn.f32x2 over output-channel pairs (exact fp32)
//   - weight fetch split across constant port (even k) and smem port (odd k)

#define H    768
#define OW   2304

typedef unsigned long long u64;

__device__ __forceinline__ u64 pack2(float lo, float hi) {
    u64 r; asm("mov.b64 %0,{%1,%2};" : "=l"(r) : "f"(lo), "f"(hi)); return r;
}
__device__ __forceinline__ void unpack2(u64 v, float& lo, float& hi) {
    asm("mov.b64 {%0,%1},%2;" : "=f"(lo), "=f"(hi) : "l"(v));
}
__device__ __forceinline__ u64 fma2(u64 a, u64 b, u64 c) {
    u64 d; asm("fma.rn.f32x2 %0,%1,%2,%3;" : "=l"(d) : "l"(a), "l"(b), "l"(c)); return d;
}

struct CPack {
    u64 W1p[3][16];   // (W1[ch][2j], W1[ch][2j+1])
    u64 b1p[16];
    u64 W2p[32][16];  // row k: (W2[k][2j], W2[k][2j+1])
    u64 b2p[16];
    u64 W3p[32][5];   // row k: (W3[k][2j], W3[k][2j+1]), padded to 10 cols
    u64 b3p[5];
};

__device__   CPack g_pack;   // staging (written by pack_kernel)
__constant__ CPack c_pack;   // constant-port copy

__global__ __launch_bounds__(256) void pack_kernel(
    const float* __restrict__ W1, const float* __restrict__ b1,
    const float* __restrict__ W2, const float* __restrict__ b2,
    const float* __restrict__ W3, const float* __restrict__ b3)
{
    const int t = threadIdx.x;
    if (t < 48) { int ch = t >> 4, j = t & 15;
                  g_pack.W1p[ch][j] = pack2(W1[ch * 32 + 2 * j], W1[ch * 32 + 2 * j + 1]); }
    if (t < 16) { g_pack.b1p[t] = pack2(b1[2 * t], b1[2 * t + 1]);
                  g_pack.b2p[t] = pack2(b2[2 * t], b2[2 * t + 1]); }
    for (int i = t; i < 512; i += 256) {
        int k = i >> 4, j = i & 15;
        g_pack.W2p[k][j] = pack2(W2[k * 32 + 2 * j], W2[k * 32 + 2 * j + 1]);
    }
    for (int i = t; i < 160; i += 256) {
        int k = i / 5, j = i - k * 5;
        float lo = W3[k * 9 + 2 * j];
        float hi = (2 * j + 1 < 9) ? W3[k * 9 + 2 * j + 1] : 0.f;
        g_pack.W3p[k][j] = pack2(lo, hi);
    }
    if (t < 5) {
        float lo = b3[2 * t];
        float hi = (2 * t + 1 < 9) ? b3[2 * t + 1] : 0.f;
        g_pack.b3p[t] = pack2(lo, hi);
    }
}

struct SM {
    float   X[3][22 * 22];       //  5808 B  input (border: pre-scaled by dinv)
    __half2 H1[16][20 * 20];     // 25600 B  layer1 out, channel pairs
    __half2 H2[16][18 * 18];     // 20736 B  layer2 out, channel pairs
    u64     W2s[32][16];         //  4096 B  smem weight mirror (odd-k source)
    u64     W3s[32][5];          //  1280 B
};                               // ~57.5 KB total -> 3 blocks/SM

__device__ __forceinline__ float dinv_at(int r, int c) {
    int rc = 1 + (r > 0) + (r < H - 1);
    int cc = 1 + (c > 0) + (c < H - 1);
    int n = rc * cc;                        // 4, 6, or 9
    return (n == 9) ? (1.0f / 3.0f)
         : ((n == 4) ? 0.5f : 0.40824829046386302f);
}

template <bool INTERIOR>
__device__ __forceinline__ void tile_compute(
    SM* sm, int tr, int tc,
    const float* __restrict__ x,
    float* __restrict__ out)
{
    const int tid = threadIdx.x;
    constexpr float NINTH = 1.0f / 9.0f;

    // ---- smem weight mirrors (odd-k port source) --------------------------
    for (int i = tid; i < 512; i += 256)
        ((u64*)sm->W2s)[i] = ((const u64*)g_pack.W2p)[i];
    for (int i = tid; i < 160; i += 256)
        ((u64*)sm->W3s)[i] = ((const u64*)g_pack.W3p)[i];

    // ---- stage 0: x tile 22x22 -------------------------------------------
    for (int i = tid; i < 484; i += 256) {
        int xr = i / 22, xc = i - xr * 22;
        int gr = tr - 3 + xr, gc = tc - 3 + xc;
        float v0 = 0.f, v1 = 0.f, v2 = 0.f;
        if (INTERIOR) {
            const float* p = x + (gr * H + gc) * 3;
            v0 = p[0]; v1 = p[1]; v2 = p[2];
        } else if ((unsigned)gr < H && (unsigned)gc < H) {
            float d = dinv_at(gr, gc);
            const float* p = x + (gr * H + gc) * 3;
            v0 = p[0] * d; v1 = p[1] * d; v2 = p[2] * d;
        }
        sm->X[0][i] = v0; sm->X[1][i] = v1; sm->X[2][i] = v2;
    }
    __syncthreads();

    // ---- stage 1: h1 on 20x20 --------------------------------------------
    for (int p = tid; p < 400; p += 256) {
        int r = p / 20, c = p - r * 20;
        int base = r * 22 + c;
        float s0 = 0.f, s1 = 0.f, s2 = 0.f;
#pragma unroll
        for (int dr = 0; dr < 3; dr++) {
            int o = base + dr * 22;
            s0 += sm->X[0][o] + sm->X[0][o + 1] + sm->X[0][o + 2];
            s1 += sm->X[1][o] + sm->X[1][o + 1] + sm->X[1][o + 2];
            s2 += sm->X[2][o] + sm->X[2][o + 1] + sm->X[2][o + 2];
        }
        int gr = tr - 2 + r, gc = tc - 2 + c;
        float scale, post;
        bool valid = true;
        if (INTERIOR) { scale = NINTH; post = 1.f; }
        else {
            valid = (unsigned)gr < H && (unsigned)gc < H;
            float d = valid ? dinv_at(gr, gc) : 0.f;
            scale = d; post = d;
        }
        s0 *= scale; s1 *= scale; s2 *= scale;

        u64 A0 = pack2(s0, s0), A1 = pack2(s1, s1), A2 = pack2(s2, s2);
#pragma unroll
        for (int j = 0; j < 16; j++) {
            u64 a = fma2(A0, c_pack.W1p[0][j], c_pack.b1p[j]);
            a = fma2(A1, c_pack.W1p[1][j], a);
            a = fma2(A2, c_pack.W1p[2][j], a);
            float lo, hi; unpack2(a, lo, hi);
            lo = fmaxf(lo, 0.f); hi = fmaxf(hi, 0.f);
            if (!INTERIOR) { lo = valid ? lo * post : 0.f; hi = valid ? hi * post : 0.f; }
            sm->H1[j][p] = __floats2half2_rn(lo, hi);
        }
    }
    __syncthreads();

    // ---- stage 2: h2 on 18x18 --------------------------------------------
    for (int p = tid; p < 324; p += 256) {
        int r = p / 18, c = p - r * 18;
        int gr = tr - 1 + r, gc = tc - 1 + c;
        float scale, post;
        bool valid = true;
        if (INTERIOR) { scale = NINTH; post = 1.f; }
        else {
            valid = (unsigned)gr < H && (unsigned)gc < H;
            float d = valid ? dinv_at(gr, gc) : 0.f;
            scale = d; post = d;
        }

        u64 acc[16];
#pragma unroll
        for (int j = 0; j < 16; j++) acc[j] = c_pack.b2p[j];

        const int base = r * 20 + c;
#pragma unroll
        for (int k8 = 0; k8 < 16; k8++) {
            const __half2* Up = sm->H1[k8] + base;
            __half2 s = __hadd2(__hadd2(Up[0], Up[1]), Up[2]);
            s = __hadd2(s, __hadd2(__hadd2(Up[20], Up[21]), Up[22]));
            s = __hadd2(s, __hadd2(__hadd2(Up[40], Up[41]), Up[42]));
            float2 sf = __half22float2(s);
            float sx = sf.x * scale, sy = sf.y * scale;
            u64 A = pack2(sx, sx), B = pack2(sy, sy);
            const u64* wc = c_pack.W2p[2 * k8];        // even k: constant port
            const u64* ws = sm->W2s[2 * k8 + 1];       // odd k:  smem port
#pragma unroll
            for (int j = 0; j < 16; j++) {
                acc[j] = fma2(A, wc[j], acc[j]);
                acc[j] = fma2(B, ws[j], acc[j]);
            }
        }
#pragma unroll
        for (int j = 0; j < 16; j++) {
            float lo, hi; unpack2(acc[j], lo, hi);
            lo = fmaxf(lo, 0.f); hi = fmaxf(hi, 0.f);
            if (!INTERIOR) { lo = valid ? lo * post : 0.f; hi = valid ? hi * post : 0.f; }
            sm->H2[j][p] = __floats2half2_rn(lo, hi);
        }
    }
    __syncthreads();

    // ---- stage 3: out 16x16, pixel-shuffled ------------------------------
    {
        int r = tid >> 4, c = tid & 15;
        int gr = tr + r, gc = tc + c;
        float scale = INTERIOR ? NINTH : dinv_at(gr, gc);

        u64 acc[5];
#pragma unroll
        for (int j = 0; j < 5; j++) acc[j] = c_pack.b3p[j];

        const int base = r * 18 + c;
#pragma unroll
        for (int k8 = 0; k8 < 16; k8++) {
            const __half2* Up = sm->H2[k8] + base;
            __half2 s = __hadd2(__hadd2(Up[0], Up[1]), Up[2]);
            s = __hadd2(s, __hadd2(__hadd2(Up[18], Up[19]), Up[20]));
            s = __hadd2(s, __hadd2(__hadd2(Up[36], Up[37]), Up[38]));
            float2 sf = __half22float2(s);
            float sx = sf.x * scale, sy = sf.y * scale;
            u64 A = pack2(sx, sx), B = pack2(sy, sy);
            const u64* wc = c_pack.W3p[2 * k8];        // even k: constant port
            const u64* ws = sm->W3s[2 * k8 + 1];       // odd k:  smem port
#pragma unroll
            for (int j = 0; j < 5; j++) {
                acc[j] = fma2(A, wc[j], acc[j]);
                acc[j] = fma2(B, ws[j], acc[j]);
            }
        }
        float v[10];
#pragma unroll
        for (int j = 0; j < 5; j++) unpack2(acc[j], v[2 * j], v[2 * j + 1]);
#pragma unroll
        for (int sy3 = 0; sy3 < 3; sy3++) {
            int row = (gr * 3 + sy3) * OW + gc * 3;
            out[row + 0] = v[sy3 * 3 + 0];
            out[row + 1] = v[sy3 * 3 + 1];
            out[row + 2] = v[sy3 * 3 + 2];
        }
    }
}

__global__ __launch_bounds__(256, 3) void fused_kernel(
    const float* __restrict__ x,
    float* __restrict__ out)
{
    extern __shared__ char smraw[];
    SM* sm = (SM*)smraw;
    const int bx = blockIdx.x, by = blockIdx.y;
    if (bx >= 1 && bx <= 46 && by >= 1 && by <= 46)
        tile_compute<true>(sm, by * 16, bx * 16, x, out);
    else
        tile_compute<false>(sm, by * 16, bx * 16, x, out);
}

// ---------------------------------------------------------------------------

extern "C" void kernel_launch(void* const* d_in, const int* in_sizes, int n_in,
                              void* d_out, int out_size)
{
    const float* x  = (const float*)d_in[0];
    // d_in[1] = edge_index: unused (static 8-neighbor grid)
    const float* W1 = (const float*)d_in[2];
    const float* b1 = (const float*)d_in[3];
    const float* W2 = (const float*)d_in[4];
    const float* b2 = (const float*)d_in[5];
    const float* W3 = (const float*)d_in[6];
    const float* b3 = (const float*)d_in[7];
    float* out = (float*)d_out;

    // One-time, outside-of-capture: attribute setting must not occur during
    // the harness's graph-capture call.
    static bool attr_set = false;
    if (!attr_set) {
        cudaFuncSetAttribute(fused_kernel,
                             cudaFuncAttributeMaxDynamicSharedMemorySize, (int)sizeof(SM));
        attr_set = true;
    }

    pack_kernel<<<1, 256>>>(W1, b1, W2, b2, W3, b3);

    // Update the constant bank with a plain capturable DtoD memcpy node.
    void* gp = nullptr;
    void* cp = nullptr;
    cudaGetSymbolAddress(&gp, g_pack);
    cudaGetSymbolAddress(&cp, c_pack);
    cudaMemcpyAsync(cp, gp, sizeof(CPack), cudaMemcpyDeviceToDevice, 0);

    fused_kernel<<<dim3(48, 48), 256, sizeof(SM)>>>(x, out);
}

// round 9
// speedup vs baseline: 1.2626x; 1.2626x over previous
#include <cuda_runtime.h>
#include <cuda_fp16.h>

// SatelliteImageGNN: 3-layer GCN on a 768x768 8-neighbor grid + 3x pixel shuffle.
//
// Transform: with dinv = 1/sqrt(deg) (position-determined on the grid),
//   layer(h) = (dinv .* BoxSum3x3(dinv .* h)) @ W + b
// edge_index is never read.
//
// R9 = R7 (fused, fp16-staged, ALL weights on the constant port) +
//   - f32x2 GEMM with row-interleaved ulonglong2 constant weights
//     (one LDC.128 feeds both fma2 of an output pair; no smem weight traffic)
//   - __launch_bounds__(256,4): 64-reg cap -> 4 blocks/SM (occ 35% -> ~47%)

#define H    768
#define OW   2304

typedef unsigned long long u64;

__device__ __forceinline__ u64 pack2(float lo, float hi) {
    u64 r; asm("mov.b64 %0,{%1,%2};" : "=l"(r) : "f"(lo), "f"(hi)); return r;
}
__device__ __forceinline__ void unpack2(u64 v, float& lo, float& hi) {
    asm("mov.b64 {%0,%1},%2;" : "=f"(lo), "=f"(hi) : "l"(v));
}
__device__ __forceinline__ u64 fma2(u64 a, u64 b, u64 c) {
    u64 d; asm("fma.rn.f32x2 %0,%1,%2,%3;" : "=l"(d) : "l"(a), "l"(b), "l"(c)); return d;
}

struct CPack {
    u64        W1p[3][16];   // (W1[ch][2j], W1[ch][2j+1])
    u64        b1p[16];
    ulonglong2 W2q[16][16];  // [k8][j] = { rows 2k8 , 2k8+1 } output-pair j
    u64        b2p[16];
    ulonglong2 W3q[16][5];   // [k8][j], COUT=9 padded to 10
    u64        b3p[5];
};

__device__   CPack g_pack;   // staging (written by pack_kernel)
__constant__ CPack c_pack;   // constant-port copy

__global__ __launch_bounds__(256) void pack_kernel(
    const float* __restrict__ W1, const float* __restrict__ b1,
    const float* __restrict__ W2, const float* __restrict__ b2,
    const float* __restrict__ W3, const float* __restrict__ b3)
{
    const int t = threadIdx.x;
    if (t < 48) { int ch = t >> 4, j = t & 15;
                  g_pack.W1p[ch][j] = pack2(W1[ch * 32 + 2 * j], W1[ch * 32 + 2 * j + 1]); }
    if (t < 16) { g_pack.b1p[t] = pack2(b1[2 * t], b1[2 * t + 1]);
                  g_pack.b2p[t] = pack2(b2[2 * t], b2[2 * t + 1]); }
    if (t < 5)  { float lo = b3[2 * t];
                  float hi = (2 * t + 1 < 9) ? b3[2 * t + 1] : 0.f;
                  g_pack.b3p[t] = pack2(lo, hi); }
    // W2q: 16 k8 x 16 j
    if (t < 256) {
        int k8 = t >> 4, j = t & 15;
        ulonglong2 w;
        w.x = pack2(W2[(2 * k8) * 32 + 2 * j],     W2[(2 * k8) * 32 + 2 * j + 1]);
        w.y = pack2(W2[(2 * k8 + 1) * 32 + 2 * j], W2[(2 * k8 + 1) * 32 + 2 * j + 1]);
        g_pack.W2q[k8][j] = w;
    }
    // W3q: 16 k8 x 5 j (pad col 9 with 0)
    if (t < 80) {
        int k8 = t / 5, j = t - k8 * 5;
        float a0 = W3[(2 * k8) * 9 + 2 * j];
        float a1 = (2 * j + 1 < 9) ? W3[(2 * k8) * 9 + 2 * j + 1] : 0.f;
        float c0 = W3[(2 * k8 + 1) * 9 + 2 * j];
        float c1 = (2 * j + 1 < 9) ? W3[(2 * k8 + 1) * 9 + 2 * j + 1] : 0.f;
        ulonglong2 w; w.x = pack2(a0, a1); w.y = pack2(c0, c1);
        g_pack.W3q[k8][j] = w;
    }
}

struct SM {
    float   X[3][22 * 22];       //  5808 B  input (border: pre-scaled by dinv)
    __half2 H1[16][20 * 20];     // 25600 B  layer1 out, channel pairs
    __half2 H2[16][18 * 18];     // 20736 B  layer2 out, channel pairs
};                               // 52144 B total -> 4 blocks/SM by smem

__device__ __forceinline__ float dinv_at(int r, int c) {
    int rc = 1 + (r > 0) + (r < H - 1);
    int cc = 1 + (c > 0) + (c < H - 1);
    int n = rc * cc;                        // 4, 6, or 9
    return (n == 9) ? (1.0f / 3.0f)
         : ((n == 4) ? 0.5f : 0.40824829046386302f);
}

template <bool INTERIOR>
__device__ __forceinline__ void tile_compute(
    SM* sm, int tr, int tc,
    const float* __restrict__ x,
    float* __restrict__ out)
{
    const int tid = threadIdx.x;
    constexpr float NINTH = 1.0f / 9.0f;

    // ---- stage 0: x tile 22x22 -------------------------------------------
    for (int i = tid; i < 484; i += 256) {
        int xr = i / 22, xc = i - xr * 22;
        int gr = tr - 3 + xr, gc = tc - 3 + xc;
        float v0 = 0.f, v1 = 0.f, v2 = 0.f;
        if (INTERIOR) {
            const float* p = x + (gr * H + gc) * 3;
            v0 = p[0]; v1 = p[1]; v2 = p[2];
        } else if ((unsigned)gr < H && (unsigned)gc < H) {
            float d = dinv_at(gr, gc);
            const float* p = x + (gr * H + gc) * 3;
            v0 = p[0] * d; v1 = p[1] * d; v2 = p[2] * d;
        }
        sm->X[0][i] = v0; sm->X[1][i] = v1; sm->X[2][i] = v2;
    }
    __syncthreads();

    // ---- stage 1: h1 on 20x20 --------------------------------------------
    for (int p = tid; p < 400; p += 256) {
        int r = p / 20, c = p - r * 20;
        int base = r * 22 + c;
        float s0 = 0.f, s1 = 0.f, s2 = 0.f;
#pragma unroll
        for (int dr = 0; dr < 3; dr++) {
            int o = base + dr * 22;
            s0 += sm->X[0][o] + sm->X[0][o + 1] + sm->X[0][o + 2];
            s1 += sm->X[1][o] + sm->X[1][o + 1] + sm->X[1][o + 2];
            s2 += sm->X[2][o] + sm->X[2][o + 1] + sm->X[2][o + 2];
        }
        int gr = tr - 2 + r, gc = tc - 2 + c;
        float scale, post;
        bool valid = true;
        if (INTERIOR) { scale = NINTH; post = 1.f; }
        else {
            valid = (unsigned)gr < H && (unsigned)gc < H;
            float d = valid ? dinv_at(gr, gc) : 0.f;
            scale = d; post = d;
        }
        s0 *= scale; s1 *= scale; s2 *= scale;

        u64 A0 = pack2(s0, s0), A1 = pack2(s1, s1), A2 = pack2(s2, s2);
#pragma unroll
        for (int j = 0; j < 16; j++) {
            u64 a = fma2(A0, c_pack.W1p[0][j], c_pack.b1p[j]);
            a = fma2(A1, c_pack.W1p[1][j], a);
            a = fma2(A2, c_pack.W1p[2][j], a);
            float lo, hi; unpack2(a, lo, hi);
            lo = fmaxf(lo, 0.f); hi = fmaxf(hi, 0.f);
            if (!INTERIOR) { lo = valid ? lo * post : 0.f; hi = valid ? hi * post : 0.f; }
            sm->H1[j][p] = __floats2half2_rn(lo, hi);
        }
    }
    __syncthreads();

    // ---- stage 2: h2 on 18x18 --------------------------------------------
    for (int p = tid; p < 324; p += 256) {
        int r = p / 18, c = p - r * 18;
        int gr = tr - 1 + r, gc = tc - 1 + c;
        float scale, post;
        bool valid = true;
        if (INTERIOR) { scale = NINTH; post = 1.f; }
        else {
            valid = (unsigned)gr < H && (unsigned)gc < H;
            float d = valid ? dinv_at(gr, gc) : 0.f;
            scale = d; post = d;
        }

        u64 acc[16];
#pragma unroll
        for (int j = 0; j < 16; j++) acc[j] = c_pack.b2p[j];

        const int base = r * 20 + c;
#pragma unroll
        for (int k8 = 0; k8 < 16; k8++) {
            const __half2* Up = sm->H1[k8] + base;
            __half2 s = __hadd2(__hadd2(Up[0], Up[1]), Up[2]);
            s = __hadd2(s, __hadd2(__hadd2(Up[20], Up[21]), Up[22]));
            s = __hadd2(s, __hadd2(__hadd2(Up[40], Up[41]), Up[42]));
            float2 sf = __half22float2(s);
            float sx = sf.x * scale, sy = sf.y * scale;
            u64 A = pack2(sx, sx), B = pack2(sy, sy);
#pragma unroll
            for (int j = 0; j < 16; j++) {
                ulonglong2 w = c_pack.W2q[k8][j];     // LDC.128, both rows
                acc[j] = fma2(A, w.x, acc[j]);
                acc[j] = fma2(B, w.y, acc[j]);
            }
        }
#pragma unroll
        for (int j = 0; j < 16; j++) {
            float lo, hi; unpack2(acc[j], lo, hi);
            lo = fmaxf(lo, 0.f); hi = fmaxf(hi, 0.f);
            if (!INTERIOR) { lo = valid ? lo * post : 0.f; hi = valid ? hi * post : 0.f; }
            sm->H2[j][p] = __floats2half2_rn(lo, hi);
        }
    }
    __syncthreads();

    // ---- stage 3: out 16x16, pixel-shuffled ------------------------------
    {
        int r = tid >> 4, c = tid & 15;
        int gr = tr + r, gc = tc + c;
        float scale = INTERIOR ? NINTH : dinv_at(gr, gc);

        u64 acc[5];
#pragma unroll
        for (int j = 0; j < 5; j++) acc[j] = c_pack.b3p[j];

        const int base = r * 18 + c;
#pragma unroll
        for (int k8 = 0; k8 < 16; k8++) {
            const __half2* Up = sm->H2[k8] + base;
            __half2 s = __hadd2(__hadd2(Up[0], Up[1]), Up[2]);
            s = __hadd2(s, __hadd2(__hadd2(Up[18], Up[19]), Up[20]));
            s = __hadd2(s, __hadd2(__hadd2(Up[36], Up[37]), Up[38]));
            float2 sf = __half22float2(s);
            float sx = sf.x * scale, sy = sf.y * scale;
            u64 A = pack2(sx, sx), B = pack2(sy, sy);
#pragma unroll
            for (int j = 0; j < 5; j++) {
                ulonglong2 w = c_pack.W3q[k8][j];     // LDC.128, both rows
                acc[j] = fma2(A, w.x, acc[j]);
                acc[j] = fma2(B, w.y, acc[j]);
            }
        }
        float v[10];
#pragma unroll
        for (int j = 0; j < 5; j++) unpack2(acc[j], v[2 * j], v[2 * j + 1]);
#pragma unroll
        for (int sy3 = 0; sy3 < 3; sy3++) {
            int row = (gr * 3 + sy3) * OW + gc * 3;
            out[row + 0] = v[sy3 * 3 + 0];
            out[row + 1] = v[sy3 * 3 + 1];
            out[row + 2] = v[sy3 * 3 + 2];
        }
    }
}

__global__ __launch_bounds__(256, 4) void fused_kernel(
    const float* __restrict__ x,
    float* __restrict__ out)
{
    extern __shared__ char smraw[];
    SM* sm = (SM*)smraw;
    const int bx = blockIdx.x, by = blockIdx.y;
    if (bx >= 1 && bx <= 46 && by >= 1 && by <= 46)
        tile_compute<true>(sm, by * 16, bx * 16, x, out);
    else
        tile_compute<false>(sm, by * 16, bx * 16, x, out);
}

// ---------------------------------------------------------------------------

extern "C" void kernel_launch(void* const* d_in, const int* in_sizes, int n_in,
                              void* d_out, int out_size)
{
    const float* x  = (const float*)d_in[0];
    // d_in[1] = edge_index: unused (static 8-neighbor grid)
    const float* W1 = (const float*)d_in[2];
    const float* b1 = (const float*)d_in[3];
    const float* W2 = (const float*)d_in[4];
    const float* b2 = (const float*)d_in[5];
    const float* W3 = (const float*)d_in[6];
    const float* b3 = (const float*)d_in[7];
    float* out = (float*)d_out;

    // One-time, outside-of-capture: attribute setting must not occur during
    // the harness's graph-capture call.
    static bool attr_set = false;
    if (!attr_set) {
        cudaFuncSetAttribute(fused_kernel,
                             cudaFuncAttributeMaxDynamicSharedMemorySize, (int)sizeof(SM));
        attr_set = true;
    }

    pack_kernel<<<1, 256>>>(W1, b1, W2, b2, W3, b3);

    // Update the constant bank with a plain capturable DtoD memcpy node.
    void* gp = nullptr;
    void* cp = nullptr;
    cudaGetSymbolAddress(&gp, g_pack);
    cudaGetSymbolAddress(&cp, c_pack);
    cudaMemcpyAsync(cp, gp, sizeof(CPack), cudaMemcpyDeviceToDevice, 0);

    fused_kernel<<<dim3(48, 48), 256, sizeof(SM)>>>(x, out);
}